// round 1
// baseline (speedup 1.0000x reference)
#include <cuda_runtime.h>
#include <math.h>

#define D          2048
#define TILE_ROWS  32
#define THREADS    256
#define CPT        8            // output columns per thread = D/THREADS
#define INV_SQRT2_F 0.70710678118654752440f
#define PI_F        3.14159265358979323846f

__device__ __forceinline__ float2 cmul(float2 a, float2 b) {
    return make_float2(fmaf(a.x, b.x, -a.y * b.y), fmaf(a.x, b.y, a.y * b.x));
}

__global__ __launch_bounds__(THREADS, 2)
void qproj_kernel(const float* __restrict__ x,
                  const float* __restrict__ W_pre,
                  const float* __restrict__ b_pre,
                  const float* __restrict__ q_weights,
                  const float* __restrict__ W_post,
                  const float* __restrict__ b_post,
                  float* __restrict__ out)
{
    // 4 separate 8KB weight arrays: LDS.128 per lane is 16B-contiguous across
    // lanes -> conflict-free crossbar access.
    __shared__ __align__(16) float wq[4][D];      // 32 KB
    __shared__ float4 araw[TILE_ROWS];            // raw (dot + b_pre) per row
    __shared__ float4 zs[TILE_ROWS];              // circuit outputs per row
    __shared__ float2 rotg[2][4][4];              // Rot gate matrices (batch-constant)
    __shared__ float  bpre_s[4];

    const int tid  = threadIdx.x;
    const int lane = tid & 31;
    const int warp = tid >> 5;
    const size_t tile_base = (size_t)blockIdx.x * TILE_ROWS;

    // ---- block setup: W_pre -> smem (float4 copy, layout identical) ----
    {
        const float4* wsrc = (const float4*)W_pre;
        float4*       wdst = (float4*)wq;
        for (int idx = tid; idx < D; idx += THREADS)   // 4*2048 floats = 2048 float4
            wdst[idx] = wsrc[idx];
    }
    if (tid < 4) bpre_s[tid] = b_pre[tid];

    // Rot gates depend only on q_weights: precompute 8 gates, one per thread.
    if (tid >= 8 && tid < 16) {
        const int g = tid - 8;
        const int l = g >> 2, q = g & 3;
        const float phi = q_weights[(l * 4 + q) * 3 + 0];
        const float th  = q_weights[(l * 4 + q) * 3 + 1];
        const float om  = q_weights[(l * 4 + q) * 3 + 2];
        float c, s;   sincosf(0.5f * th, &s, &c);
        float sp, cp; sincosf(0.5f * (phi + om), &sp, &cp);
        float sm, cm; sincosf(0.5f * (phi - om), &sm, &cm);
        // ep = e^{-i(phi+om)/2} = (cp,-sp); em = e^{+i(phi-om)/2} = (cm,+sm)
        rotg[l][q][0] = make_float2( cp * c, -sp * c);   // ep*c
        rotg[l][q][1] = make_float2(-cm * s, -sm * s);   // -em*s
        rotg[l][q][2] = make_float2( cm * s, -sm * s);   // conj(em)*s
        rotg[l][q][3] = make_float2( cp * c,  sp * c);   // conj(ep)*c
    }

    // Per-thread register cache of W_post rows + bias for 8 fixed columns.
    const int col0 = tid * CPT;
    float4 wp[CPT];
    float  bp[CPT];
#pragma unroll
    for (int j = 0; j < CPT; j++) {
        wp[j] = __ldg(((const float4*)W_post) + col0 + j);  // W_post[j][0..3]
        bp[j] = __ldg(b_post + col0 + j);
    }
    __syncthreads();

    // ---- Phase A: dot products. Each warp handles 4 rows together so each
    //      weight LDS.128 is amortized over 4 FMA groups. ----
    {
        const int r0 = warp * 4;
        const float4* xp[4];
#pragma unroll
        for (int r = 0; r < 4; r++)
            xp[r] = (const float4*)(x + (tile_base + r0 + r) * (size_t)D);

        float acc[4][4] = {};   // [row][qubit]
#pragma unroll
        for (int i = 0; i < D / 128; i++) {     // 16 iterations
            const int kv = i * 32 + lane;       // float4 index within row
            float4 xv[4];
#pragma unroll
            for (int r = 0; r < 4; r++) xv[r] = xp[r][kv];
            const int k = kv * 4;
            float4 wv[4];
#pragma unroll
            for (int q = 0; q < 4; q++) wv[q] = *(const float4*)&wq[q][k];
#pragma unroll
            for (int r = 0; r < 4; r++)
#pragma unroll
                for (int q = 0; q < 4; q++)
                    acc[r][q] = fmaf(xv[r].x, wv[q].x,
                                fmaf(xv[r].y, wv[q].y,
                                fmaf(xv[r].z, wv[q].z,
                                fmaf(xv[r].w, wv[q].w, acc[r][q]))));
        }
        // warp butterfly reduce all 16 accumulators
#pragma unroll
        for (int r = 0; r < 4; r++)
#pragma unroll
            for (int q = 0; q < 4; q++)
#pragma unroll
                for (int o = 16; o; o >>= 1)
                    acc[r][q] += __shfl_xor_sync(0xffffffffu, acc[r][q], o);
        if (lane == 0) {
#pragma unroll
            for (int r = 0; r < 4; r++)
                araw[r0 + r] = make_float4(acc[r][0] + bpre_s[0],
                                           acc[r][1] + bpre_s[1],
                                           acc[r][2] + bpre_s[2],
                                           acc[r][3] + bpre_s[3]);
        }
    }
    __syncthreads();

    // ---- Phase B: 4-qubit circuit, one row per thread (tid < 32). ----
    if (tid < TILE_ROWS) {
        const float4 ar = araw[tid];
        const float f[4] = { PI_F * tanhf(ar.x), PI_F * tanhf(ar.y),
                             PI_F * tanhf(ar.z), PI_F * tanhf(ar.w) };

        // Initial layer is a product state: v_w = RZ*RY*H |0>
        float2 v0[4], v1[4];
#pragma unroll
        for (int w = 0; w < 4; w++) {
            float sy, cy; sincosf(0.5f * atanf(f[w]), &sy, &cy);
            float sz, cz; sincosf(0.5f * atanf(f[w] * f[w]), &sz, &cz);
            const float r0 = INV_SQRT2_F * (cy - sy);
            const float r1 = INV_SQRT2_F * (cy + sy);
            v0[w] = make_float2(r0 * cz, -r0 * sz);
            v1[w] = make_float2(r1 * cz,  r1 * sz);
        }
        // Outer product -> 16 amplitudes. Index bit of qubit w is (3-w) (MSB = qubit 0).
        float2 st[16];
        {
            float2 t2[2] = { v0[0], v1[0] };
            float2 t4[4];
#pragma unroll
            for (int a = 0; a < 2; a++) { t4[a*2+0] = cmul(t2[a], v0[1]); t4[a*2+1] = cmul(t2[a], v1[1]); }
            float2 t8[8];
#pragma unroll
            for (int a = 0; a < 4; a++) { t8[a*2+0] = cmul(t4[a], v0[2]); t8[a*2+1] = cmul(t4[a], v1[2]); }
#pragma unroll
            for (int a = 0; a < 8; a++) { st[a*2+0] = cmul(t8[a], v0[3]); st[a*2+1] = cmul(t8[a], v1[3]); }
        }
        // Entangling layers
#pragma unroll
        for (int l = 0; l < 2; l++) {
            // 4 CNOTs (c -> (c+1)%4): pure compile-time register permutations
#pragma unroll
            for (int c = 0; c < 4; c++) {
                const int t  = (c + 1) & 3;
                const int pc = 3 - c, pt = 3 - t;
                float2 tmp[16];
#pragma unroll
                for (int i = 0; i < 16; i++)
                    tmp[i] = st[((i >> pc) & 1) ? (i ^ (1 << pt)) : i];
#pragma unroll
                for (int i = 0; i < 16; i++) st[i] = tmp[i];
            }
            // Rot on each qubit
#pragma unroll
            for (int q = 0; q < 4; q++) {
                const float2 g00 = rotg[l][q][0], g01 = rotg[l][q][1];
                const float2 g10 = rotg[l][q][2], g11 = rotg[l][q][3];
                const int m = 1 << (3 - q);
#pragma unroll
                for (int i = 0; i < 16; i++) {
                    if ((i & m) == 0) {
                        const float2 s0 = st[i], s1 = st[i | m];
                        const float2 a = cmul(g00, s0), b = cmul(g01, s1);
                        const float2 c2 = cmul(g10, s0), d = cmul(g11, s1);
                        st[i]     = make_float2(a.x + b.x,  a.y + b.y);
                        st[i | m] = make_float2(c2.x + d.x, c2.y + d.y);
                    }
                }
            }
        }
        // Measurement: z_w = sum (+/-) |amp|^2
        float z[4] = {0.f, 0.f, 0.f, 0.f};
#pragma unroll
        for (int i = 0; i < 16; i++) {
            const float p = st[i].x * st[i].x + st[i].y * st[i].y;
#pragma unroll
            for (int w = 0; w < 4; w++)
                z[w] += ((i >> (3 - w)) & 1) ? -p : p;
        }
        zs[tid] = make_float4(z[0], z[1], z[2], z[3]);
    }
    __syncthreads();

    // ---- Phase C: out[row][j] = z . W_post[j] + b_post[j], weights in regs. ----
#pragma unroll 4
    for (int r = 0; r < TILE_ROWS; r++) {
        const float4 z = zs[r];                  // broadcast LDS
        float4* op = (float4*)(out + (tile_base + r) * (size_t)D + col0);
#pragma unroll
        for (int jj = 0; jj < CPT; jj += 4) {
            float4 o;
            o.x = fmaf(z.x, wp[jj+0].x, fmaf(z.y, wp[jj+0].y, fmaf(z.z, wp[jj+0].z, fmaf(z.w, wp[jj+0].w, bp[jj+0]))));
            o.y = fmaf(z.x, wp[jj+1].x, fmaf(z.y, wp[jj+1].y, fmaf(z.z, wp[jj+1].z, fmaf(z.w, wp[jj+1].w, bp[jj+1]))));
            o.z = fmaf(z.x, wp[jj+2].x, fmaf(z.y, wp[jj+2].y, fmaf(z.z, wp[jj+2].z, fmaf(z.w, wp[jj+2].w, bp[jj+2]))));
            o.w = fmaf(z.x, wp[jj+3].x, fmaf(z.y, wp[jj+3].y, fmaf(z.z, wp[jj+3].z, fmaf(z.w, wp[jj+3].w, bp[jj+3]))));
            op[jj >> 2] = o;
        }
    }
}

extern "C" void kernel_launch(void* const* d_in, const int* in_sizes, int n_in,
                              void* d_out, int out_size)
{
    const float* x      = (const float*)d_in[0];
    const float* W_pre  = (const float*)d_in[1];
    const float* b_pre  = (const float*)d_in[2];
    const float* qw     = (const float*)d_in[3];
    const float* W_post = (const float*)d_in[4];
    const float* b_post = (const float*)d_in[5];
    float* out = (float*)d_out;

    const int rows = in_sizes[0] / D;            // 32768
    qproj_kernel<<<rows / TILE_ROWS, THREADS>>>(x, W_pre, b_pre, qw, W_post, b_post, out);
}